// round 1
// baseline (speedup 1.0000x reference)
#include <cuda_runtime.h>
#include <cstdint>

#define HH 1024
#define WW 1024
#define XV 4      // output pixels per thread in x (one float4)
#define RWS 16    // output rows per thread strip

__device__ __forceinline__ void loadrow(float* wr, const float* __restrict__ ip,
                                        int y, int x0, bool interior_x, float INFv) {
    if (y < 0 || y >= HH) {
#pragma unroll
        for (int c = 0; c < 12; ++c) wr[c] = INFv;
    } else if (interior_x) {
        const float4* p = reinterpret_cast<const float4*>(ip + (size_t)y * WW + (x0 - 4));
        float4 a = p[0], b = p[1], c4 = p[2];
        wr[0] = a.x;  wr[1] = a.y;  wr[2] = a.z;  wr[3] = a.w;
        wr[4] = b.x;  wr[5] = b.y;  wr[6] = b.z;  wr[7] = b.w;
        wr[8] = c4.x; wr[9] = c4.y; wr[10] = c4.z; wr[11] = c4.w;
    } else {
#pragma unroll
        for (int c = 0; c < 12; ++c) {
            int col = x0 - 4 + c;
            wr[c] = (col >= 0 && col < WW) ? ip[(size_t)y * WW + col] : INFv;
        }
    }
}

__global__ __launch_bounds__(128)
void erosion5x5_kernel(const float* __restrict__ img,
                       const float* __restrict__ filt,
                       float* __restrict__ out) {
    const int x0 = (blockIdx.x * blockDim.x + threadIdx.x) * XV;
    const int y0 = blockIdx.y * RWS;
    const size_t plane = (size_t)blockIdx.z * (size_t)HH * (size_t)WW;
    const float* ip = img + plane;
    float* op = out + plane;

    // Filter into registers (25 values, L1-hot loads, hoisted by full unroll)
    float fv[25];
#pragma unroll
    for (int t = 0; t < 25; ++t) fv[t] = filt[t];

    const float INFv = __int_as_float(0x7f800000);
    const bool interior_x = (x0 >= 4) && (x0 + 8 <= WW);

    // Rolling raw window: slot k%5 holds input row y0+k-2.
    float w[5][12];

    // Prologue: rows y0-2 .. y0+1 into slots 0..3
#pragma unroll
    for (int k = 0; k < 4; ++k)
        loadrow(w[k], ip, y0 + k - 2, x0, interior_x, INFv);

#pragma unroll
    for (int r = 0; r < RWS; ++r) {
        // Bring in input row y0+r+2 (slot (r+4)%5)
        loadrow(w[(r + 4) % 5], ip, y0 + r + 2, x0, interior_x, INFv);

        float acc[XV];
        // First tap (i=0,j=0): plain assignment, saves 4 mins
        {
            const int s = r % 5;
            const float f0 = fv[0];
#pragma unroll
            for (int c = 0; c < XV; ++c) acc[c] = w[s][c + 2] - f0;
        }
#pragma unroll
        for (int i = 0; i < 5; ++i) {
            const int s = (r + i) % 5;  // input row y0+r+i-2
#pragma unroll
            for (int j = 0; j < 5; ++j) {
                if (i == 0 && j == 0) continue;
                const float f = fv[i * 5 + j];
#pragma unroll
                for (int c = 0; c < XV; ++c) {
                    // w index: (x0+c+j-2) - (x0-4) = c + j + 2
                    acc[c] = fminf(acc[c], w[s][c + j + 2] - f);
                }
            }
        }

        float4 o;
        o.x = acc[0]; o.y = acc[1]; o.z = acc[2]; o.w = acc[3];
        *reinterpret_cast<float4*>(op + (size_t)(y0 + r) * WW + x0) = o;
    }
}

extern "C" void kernel_launch(void* const* d_in, const int* in_sizes, int n_in,
                              void* d_out, int out_size) {
    const float* image = (const float*)d_in[0];
    const float* filt  = (const float*)d_in[1];
    float* out = (float*)d_out;

    const int planes = in_sizes[0] / (HH * WW);  // 32*3 = 96

    dim3 block(128, 1, 1);
    dim3 grid(WW / (128 * XV), HH / RWS, planes);  // (2, 64, 96)
    erosion5x5_kernel<<<grid, block>>>(image, filt, out);
}